// round 10
// baseline (speedup 1.0000x reference)
#include <cuda_runtime.h>
#include <cstdint>

// ---------------------------------------------------------------------------
// LinearAttention B=4 N=8192 D=1024 H=16 Dh=64
// sm_100 base-ISA: mma.sync tf32 + ldmatrix + cp.async. 2 CTAs/SM GEMM.
// ---------------------------------------------------------------------------

constexpr int GM = 32768, GN = 1024, GK = 1024;
constexpr int BM = 128, BN = 128, BK = 32;
constexpr int NKT = GK / BK;                     // 32
constexpr int A_STAGE_B = BM * 128;              // 16384 B
constexpr int B_STAGE_B = BN * 128;              // 16384 B
constexpr int STAGE_B   = A_STAGE_B + B_STAGE_B; // 32768 B
constexpr int STAGES = 3;                        // ring, prefetch dist 2
constexpr int OFF_BIAS  = STAGES * STAGE_B;      // 98304
constexpr int GEMM_SMEM = OFF_BIAS + BN * 4;     // 98816 -> 2 CTAs/SM
constexpr int SCORES_SMEM = (4096 + 64 + 256 * 65) * 4;  // 83200

// scratch (device globals; no allocation allowed)
__device__ float g_X[(size_t)GM * GN];
__device__ float g_Q[(size_t)GM * GN];
__device__ float g_K[(size_t)GM * GN];
__device__ float g_V[(size_t)GM * GN];
__device__ float g_S[(size_t)GM * GN];
__device__ float g_WT[4][(size_t)GK * GN];       // W^T (n-major), tf32-rounded
__device__ float g_kvpart[1024 * 4160];
__device__ float g_kv[64 * 4096];
__device__ float g_ksum[64 * 64];

// ---------------------------------------------------------------------------
// helpers
// ---------------------------------------------------------------------------
__device__ __forceinline__ uint32_t smem_u32(const void* p) {
    uint32_t a;
    asm("{ .reg .u64 t; cvta.to.shared.u64 t, %1; cvt.u32.u64 %0, t; }" : "=r"(a) : "l"(p));
    return a;
}
__device__ __forceinline__ uint32_t f2tf(float x) {
    uint32_t r;
    asm("cvt.rna.tf32.f32 %0, %1;" : "=r"(r) : "f"(x));
    return r;
}
__device__ __forceinline__ float rna_tf32(float x) { return __uint_as_float(f2tf(x)); }

__device__ __forceinline__ void cp16(uint32_t s, const void* g) {
    asm volatile("cp.async.cg.shared.global [%0], [%1], 16;" :: "r"(s), "l"(g) : "memory");
}
#define CP_COMMIT() asm volatile("cp.async.commit_group;" ::: "memory")

__device__ __forceinline__ float fm_act(float x) { return x > 0.0f ? x + 1.0f : __expf(x); }

__device__ __forceinline__ void ldsm4(uint32_t* d, uint32_t addr) {
    asm volatile("ldmatrix.sync.aligned.m8n8.x4.shared.b16 {%0,%1,%2,%3}, [%4];"
                 : "=r"(d[0]), "=r"(d[1]), "=r"(d[2]), "=r"(d[3]) : "r"(addr));
}
__device__ __forceinline__ void mma_tf32(float* c, const uint32_t* a, uint32_t b0, uint32_t b1) {
    asm volatile(
        "mma.sync.aligned.m16n8k8.row.col.f32.tf32.tf32.f32 "
        "{%0,%1,%2,%3}, {%4,%5,%6,%7}, {%8,%9}, {%0,%1,%2,%3};"
        : "+f"(c[0]), "+f"(c[1]), "+f"(c[2]), "+f"(c[3])
        : "r"(a[0]), "r"(a[1]), "r"(a[2]), "r"(a[3]), "r"(b0), "r"(b1));
}

#define SWZ(off) ((off) ^ (((off) >> 3) & 0x70))

// ---------------------------------------------------------------------------
// pre-passes
// ---------------------------------------------------------------------------
__global__ void round_x_kernel(const float* __restrict__ x) {
    size_t i = ((size_t)blockIdx.x * 128 + threadIdx.x) * 4;
    float4 v = *reinterpret_cast<const float4*>(x + i);
    v.x = rna_tf32(v.x); v.y = rna_tf32(v.y); v.z = rna_tf32(v.z); v.w = rna_tf32(v.w);
    *reinterpret_cast<float4*>(g_X + i) = v;
}

__global__ void transpose_w_kernel(const float* __restrict__ w0, const float* __restrict__ w1,
                                   const float* __restrict__ w2, const float* __restrict__ w3) {
    __shared__ float tile[32][33];
    const float* W = (blockIdx.z == 0) ? w0 : (blockIdx.z == 1) ? w1 : (blockIdx.z == 2) ? w2 : w3;
    float* WT = &g_WT[blockIdx.z][0];
    int bx = blockIdx.x * 32, by = blockIdx.y * 32;   // bx: n, by: k
    int tx = threadIdx.x, ty = threadIdx.y;
#pragma unroll
    for (int i = 0; i < 32; i += 8)
        tile[ty + i][tx] = W[(size_t)(by + ty + i) * GN + bx + tx];
    __syncthreads();
#pragma unroll
    for (int i = 0; i < 32; i += 8)
        WT[(size_t)(bx + ty + i) * GK + by + tx] = rna_tf32(tile[tx][ty + i]);
}

// ---------------------------------------------------------------------------
// TF32 mma.sync GEMM, 3-stage ring, 2 CTAs/SM, ldmatrix fragments.
// 256 threads, warps 4(m) x 2(n); warp tile 32x64.
// Schedule: at iter kt -> wait_group(1|0), barrier, prefetch kt+2 into slot
// (kt+2)%3 == (kt-1)%3 (drained before this barrier), compute slot kt%3.
// ---------------------------------------------------------------------------
template <int MODE>
__global__ void __launch_bounds__(256, 2)
tc_gemm(const float* __restrict__ bias0, const float* __restrict__ bias1,
        const float* __restrict__ bias2, float* __restrict__ Oout)
{
    extern __shared__ __align__(128) char smem[];
    const uint32_t sb = smem_u32(smem);
    const int t = threadIdx.x, lane = t & 31, wid = t >> 5;
    const int z = blockIdx.z;

    const float* A;  const float* WT;  const float* bias;  float* O;  bool act;
    if (MODE == 0) {
        A = g_X; WT = &g_WT[z][0];
        bias = (z == 0) ? bias0 : (z == 1) ? bias1 : bias2;
        O = (z == 0) ? g_Q : (z == 1) ? g_K : g_V;
        act = (z < 2);
    } else {
        A = g_S; WT = &g_WT[3][0]; bias = bias0; O = Oout; act = false;
    }

    const int rowBase = blockIdx.y * BM;
    const int colBase = blockIdx.x * BN;
    const int wm = (wid & 3) * 32;      // 4 warps over 128 m
    const int wn = (wid >> 2) * 64;     // 2 warps over 128 n

    float* bias_s = reinterpret_cast<float*>(smem + OFF_BIAS);
    if (t < BN) bias_s[t] = bias[colBase + t];

    // ---- cp.async stage loader (SW128-swizzled 128B rows) ----
    auto load_stage = [&](int kt, int s) {
        const uint32_t stg = sb + s * STAGE_B;
        const float* Ag = A + (size_t)rowBase * GK + kt * BK;
        const float* Bg = WT + (size_t)colBase * GK + kt * BK;
#pragma unroll
        for (int i = 0; i < 4; i++) {               // A: 1024 x 16B
            int c = i * 256 + t;
            int row = c >> 3, c8 = c & 7;
            cp16(stg + SWZ(row * 128 + c8 * 16), Ag + (size_t)row * GK + c8 * 4);
        }
#pragma unroll
        for (int i = 0; i < 4; i++) {               // B: 1024 x 16B
            int c = i * 256 + t;
            int n = c >> 3, c8 = c & 7;
            cp16(stg + A_STAGE_B + SWZ(n * 128 + c8 * 16), Bg + (size_t)n * GK + c8 * 4);
        }
        CP_COMMIT();
    };

    // ---- per-lane ldmatrix address prep (validated in round 7) ----
    const int rA0 = wm + ((lane >> 3) & 1) * 8 + (lane & 7);
    const uint32_t xorA = (uint32_t)(rA0 & 7) * 16;
    const uint32_t cAb  = (uint32_t)(lane >> 4) * 16;
    const int nB0 = wn + (lane >> 4) * 8 + (lane & 7);
    const uint32_t xorB = (uint32_t)(nB0 & 7) * 16;
    const uint32_t cBb  = (uint32_t)((lane >> 3) & 1) * 16;

    float acc[2][8][4] = {};

    load_stage(0, 0);
    load_stage(1, 1);

    for (int kt = 0; kt < NKT; kt++) {
        if (kt < NKT - 1) asm volatile("cp.async.wait_group 1;" ::: "memory");
        else              asm volatile("cp.async.wait_group 0;" ::: "memory");
        __syncthreads();

        if (kt + 2 < NKT) load_stage(kt + 2, (kt + 2) % 3);

        const int s = kt % 3;
        const uint32_t aBase0 = sb + s * STAGE_B + (uint32_t)rA0 * 128;
        const uint32_t bBase  = sb + s * STAGE_B + A_STAGE_B + (uint32_t)nB0 * 128;

#pragma unroll
        for (int ks = 0; ks < 4; ks++) {
            const uint32_t cA = (uint32_t)ks * 32 + cAb;
            const uint32_t cB = (uint32_t)ks * 32 + cBb;
            uint32_t afr[2][4];
            ldsm4(afr[0], aBase0 + (cA ^ xorA));
            ldsm4(afr[1], aBase0 + 16 * 128 + (cA ^ xorA));
            uint32_t bfr[8][2];
#pragma unroll
            for (int nj = 0; nj < 4; nj++) {         // covers ni = 2nj, 2nj+1
                uint32_t d[4];
                ldsm4(d, bBase + (uint32_t)nj * 2048 + (cB ^ xorB));
                bfr[2 * nj][0] = d[0]; bfr[2 * nj][1] = d[1];
                bfr[2 * nj + 1][0] = d[2]; bfr[2 * nj + 1][1] = d[3];
            }
#pragma unroll
            for (int mi = 0; mi < 2; mi++)
#pragma unroll
                for (int ni = 0; ni < 8; ni++)
                    mma_tf32(acc[mi][ni], afr[mi], bfr[ni][0], bfr[ni][1]);
        }
    }

    // ---- epilogue ----
    const int g = lane >> 2, l4 = lane & 3;
#pragma unroll
    for (int mi = 0; mi < 2; mi++) {
        const size_t r0 = (size_t)rowBase + wm + mi * 16 + g;
#pragma unroll
        for (int ni = 0; ni < 8; ni++) {
            const int c = wn + ni * 8 + 2 * l4;
            const float b0v = bias_s[c], b1v = bias_s[c + 1];
            float v0 = acc[mi][ni][0] + b0v;
            float v1 = acc[mi][ni][1] + b1v;
            float v2 = acc[mi][ni][2] + b0v;
            float v3 = acc[mi][ni][3] + b1v;
            if (act) { v0 = fm_act(v0); v1 = fm_act(v1); v2 = fm_act(v2); v3 = fm_act(v3); }
            *reinterpret_cast<float2*>(&O[r0 * GN + colBase + c])       = make_float2(v0, v1);
            *reinterpret_cast<float2*>(&O[(r0 + 8) * GN + colBase + c]) = make_float2(v2, v3);
        }
    }
}

// ---------------------------------------------------------------------------
// kv partial + reduce (deterministic two-pass)
// ---------------------------------------------------------------------------
__global__ void kv_partial_kernel()
{
    __shared__ float ks_[32 * 64];
    __shared__ float vs_[32 * 64];
    const int chunk = blockIdx.x, h = blockIdx.y, b = blockIdx.z;
    const int t  = threadIdx.x;
    const int td = (t >> 4) * 4;
    const int te = (t & 15) * 4;

    float acc[4][4] = {};
    float ksacc[4]  = {};

    const size_t base = ((size_t)b * 8192) * 1024 + (size_t)h * 64;
    const float* Kb = g_K + base;
    const float* Vb = g_V + base;

    const int nStart = chunk * 512;
    for (int n0 = nStart; n0 < nStart + 512; n0 += 32) {
        __syncthreads();
#pragma unroll
        for (int i = 0; i < 2; i++) {
            int f  = i * 256 + t;
            int nn = f >> 4, c4 = (f & 15) * 4;
            *reinterpret_cast<float4*>(&ks_[nn * 64 + c4]) =
                *reinterpret_cast<const float4*>(&Kb[(size_t)(n0 + nn) * 1024 + c4]);
            *reinterpret_cast<float4*>(&vs_[nn * 64 + c4]) =
                *reinterpret_cast<const float4*>(&Vb[(size_t)(n0 + nn) * 1024 + c4]);
        }
        __syncthreads();
#pragma unroll 4
        for (int nn = 0; nn < 32; nn++) {
            float4 kk = *reinterpret_cast<const float4*>(&ks_[nn * 64 + td]);
            float4 vv = *reinterpret_cast<const float4*>(&vs_[nn * 64 + te]);
            float kq[4] = {kk.x, kk.y, kk.z, kk.w};
            float vq[4] = {vv.x, vv.y, vv.z, vv.w};
#pragma unroll
            for (int i = 0; i < 4; i++)
#pragma unroll
                for (int j = 0; j < 4; j++)
                    acc[i][j] += kq[i] * vq[j];
            if (te == 0) {
                ksacc[0] += kk.x; ksacc[1] += kk.y; ksacc[2] += kk.z; ksacc[3] += kk.w;
            }
        }
    }

    float* P = g_kvpart + (size_t)(((b * 16 + h) * 16) + chunk) * 4160;
#pragma unroll
    for (int i = 0; i < 4; i++)
#pragma unroll
        for (int j = 0; j < 4; j++)
            P[(td + i) * 64 + te + j] = acc[i][j];
    if (te == 0) {
#pragma unroll
        for (int i = 0; i < 4; i++) P[4096 + td + i] = ksacc[i];
    }
}

__global__ void kv_reduce_kernel()
{
    const int bh = blockIdx.x;
    const float* P = g_kvpart + (size_t)bh * 16 * 4160;
    for (int i = threadIdx.x; i < 4160; i += 256) {
        float s = 0.0f;
#pragma unroll
        for (int c = 0; c < 16; c++) s += P[c * 4160 + i];
        if (i < 4096) g_kv[bh * 4096 + i] = s;
        else          g_ksum[bh * 64 + (i - 4096)] = s;
    }
}

// ---------------------------------------------------------------------------
// scores: 2-row register blocking; output rna-rounded (feeds tf32 GEMM2).
// ---------------------------------------------------------------------------
__global__ void __launch_bounds__(128)
scores_kernel()
{
    extern __shared__ float sm[];
    float* kv_s   = sm;               // 4096
    float* ksum_s = sm + 4096;        // 64
    float* q_s    = sm + 4160;        // 256 * 65

    const int h  = blockIdx.y;
    const int r0 = blockIdx.x * 256;
    const int b  = r0 >> 13;
    const int bh = b * 16 + h;
    const int t  = threadIdx.x;

    for (int i = t; i < 4096; i += 128) kv_s[i] = g_kv[bh * 4096 + i];
    if (t < 64) ksum_s[t] = g_ksum[bh * 64 + t];

#pragma unroll
    for (int i = 0; i < 32; i++) {
        int f = i * 128 + t;
        int row = f >> 4, c4 = (f & 15) << 2;
        float4 qv = *reinterpret_cast<const float4*>(
            &g_Q[(size_t)(r0 + row) * 1024 + h * 64 + c4]);
        float* dst = &q_s[row * 65 + c4];
        dst[0] = qv.x; dst[1] = qv.y; dst[2] = qv.z; dst[3] = qv.w;
    }
    __syncthreads();

    float accA[64], accB[64];
#pragma unroll
    for (int e = 0; e < 64; e++) { accA[e] = 0.0f; accB[e] = 0.0f; }
    float zA = 0.0f, zB = 0.0f;
    const float* qa = &q_s[t * 65];
    const float* qb = &q_s[(t + 128) * 65];

    for (int d = 0; d < 64; d++) {
        float q0 = qa[d], q1 = qb[d];
        float ks = ksum_s[d];
        zA += q0 * ks;  zB += q1 * ks;
        const float4* kr = reinterpret_cast<const float4*>(&kv_s[d * 64]);
#pragma unroll
        for (int e4 = 0; e4 < 16; e4++) {
            float4 kv4 = kr[e4];
            accA[e4 * 4 + 0] += q0 * kv4.x;  accB[e4 * 4 + 0] += q1 * kv4.x;
            accA[e4 * 4 + 1] += q0 * kv4.y;  accB[e4 * 4 + 1] += q1 * kv4.y;
            accA[e4 * 4 + 2] += q0 * kv4.z;  accB[e4 * 4 + 2] += q1 * kv4.z;
            accA[e4 * 4 + 3] += q0 * kv4.w;  accB[e4 * 4 + 3] += q1 * kv4.w;
        }
    }

    __syncthreads();
    float zvA = 1.0f / (zA + 1e-6f);
    float zvB = 1.0f / (zB + 1e-6f);
#pragma unroll
    for (int e = 0; e < 64; e++) {
        q_s[t * 65 + e]         = rna_tf32(accA[e] * zvA);
        q_s[(t + 128) * 65 + e] = rna_tf32(accB[e] * zvB);
    }
    __syncthreads();

#pragma unroll
    for (int i = 0; i < 32; i++) {
        int f = i * 128 + t;
        int row = f >> 4, c4 = (f & 15) << 2;
        const float* src = &q_s[row * 65 + c4];
        float4 o = make_float4(src[0], src[1], src[2], src[3]);
        *reinterpret_cast<float4*>(&g_S[(size_t)(r0 + row) * 1024 + h * 64 + c4]) = o;
    }
}

// ---------------------------------------------------------------------------
// launch
// ---------------------------------------------------------------------------
extern "C" void kernel_launch(void* const* d_in, const int* in_sizes, int n_in,
                              void* d_out, int out_size)
{
    const float* x  = (const float*)d_in[0];
    const float* wq = (const float*)d_in[1];
    const float* bq = (const float*)d_in[2];
    const float* wk = (const float*)d_in[3];
    const float* bk = (const float*)d_in[4];
    const float* wv = (const float*)d_in[5];
    const float* bv = (const float*)d_in[6];
    const float* wo = (const float*)d_in[7];
    const float* bo = (const float*)d_in[8];
    float* out = (float*)d_out;
    (void)in_sizes; (void)n_in; (void)out_size;

    cudaFuncSetAttribute(tc_gemm<0>, cudaFuncAttributeMaxDynamicSharedMemorySize, GEMM_SMEM);
    cudaFuncSetAttribute(tc_gemm<1>, cudaFuncAttributeMaxDynamicSharedMemorySize, GEMM_SMEM);
    cudaFuncSetAttribute(scores_kernel, cudaFuncAttributeMaxDynamicSharedMemorySize, SCORES_SMEM);

    // 0) rna-round operands (HMMA truncation then exact)
    round_x_kernel<<<65536, 128>>>(x);
    transpose_w_kernel<<<dim3(32, 32, 4), dim3(32, 8)>>>(wq, wk, wv, wo);

    // 1) QKV projections
    tc_gemm<0><<<dim3(GN / BN, GM / BM, 3), 256, GEMM_SMEM>>>(bq, bk, bv, nullptr);

    // 2) kv outer-product + ksum
    kv_partial_kernel<<<dim3(16, 16, 4), 256>>>();
    kv_reduce_kernel<<<64, 256>>>();

    // 3) scores = (q @ kv) * z  (rna-rounded output)
    scores_kernel<<<dim3(128, 16), 128, SCORES_SMEM>>>();

    // 4) out = scores @ wo + bo
    tc_gemm<1><<<dim3(GN / BN, GM / BM, 1), 256, GEMM_SMEM>>>(bo, nullptr, nullptr, out);
}